// round 15
// baseline (speedup 1.0000x reference)
#include <cuda_runtime.h>
#include <cstdint>
#include <math.h>

#define Hdim  1024
#define NH    16
#define DH    64
#define BATCH 2
#define Ss    2048
#define MT    (BATCH * Ss)

// Scratch (no allocs allowed). g_v holds V TRANSPOSED: [b*1024 + h*64 + d][token]
__device__ float g_q[MT * Hdim];
__device__ float g_k[MT * Hdim];
__device__ float g_v[MT * Hdim];
__device__ float g_o[MT * Hdim];

// ======================= helpers =======================
__device__ __forceinline__ uint32_t s2u(const void* p) {
    uint32_t a;
    asm("{ .reg .u64 t; cvta.to.shared.u64 t, %1; cvt.u32.u64 %0, t; }"
        : "=r"(a) : "l"(p));
    return a;
}
__device__ __forceinline__ float tf32r(float x) {
    uint32_t u;
    asm("cvt.rna.tf32.f32 %0, %1;" : "=r"(u) : "f"(x));
    return __uint_as_float(u);
}
__device__ __forceinline__ uint32_t tf32u(float x) {
    uint32_t u;
    asm("cvt.rna.tf32.f32 %0, %1;" : "=r"(u) : "f"(x));
    return u;
}
__device__ __forceinline__ void mma8(float* c, const uint32_t* a, const uint32_t* b) {
    asm volatile(
        "mma.sync.aligned.m16n8k8.row.col.f32.tf32.tf32.f32 "
        "{%0,%1,%2,%3}, {%4,%5,%6,%7}, {%8,%9}, {%0,%1,%2,%3};\n"
        : "+f"(c[0]), "+f"(c[1]), "+f"(c[2]), "+f"(c[3])
        : "r"(a[0]), "r"(a[1]), "r"(a[2]), "r"(a[3]), "r"(b[0]), "r"(b[1]));
}
__device__ __forceinline__ void cpa16(uint32_t dst, const void* src) {
    asm volatile("cp.async.cg.shared.global [%0], [%1], 16;" :: "r"(dst), "l"(src));
}
#define CPCOMMIT() asm volatile("cp.async.commit_group;" ::: "memory")
#define CPWAIT0()  asm volatile("cp.async.wait_group 0;" ::: "memory")
#define CPWAIT1()  asm volatile("cp.async.wait_group 1;" ::: "memory")

__device__ __forceinline__ float sigm(float x) {
    return __fdividef(1.0f, 1.0f + __expf(-0.125f * x));
}

// ======================= projection GEMM (cp.async 2-stage) =======================
// MODE 0: plain fp32 out (final proj). MODE 1: tf32-rounded out (Q, K).
// MODE 3: tf32-rounded + TRANSPOSED out for V: out[(b*1024 + col)*2048 + token].
#define GP  36
#define GST (128 * GP)
#define GSMEM (4 * GST * 4)

template <int MODE>
__global__ void __launch_bounds__(256, 2) gemm_mma(
    const float* __restrict__ A, const float* __restrict__ W,
    const float* __restrict__ bias, float* __restrict__ out)
{
    extern __shared__ float gsm[];
    float* As = gsm;             // [2][GST]
    float* Bs = gsm + 2 * GST;   // [2][GST]

    const int tid = threadIdx.x, wid = tid >> 5, lane = tid & 31;
    const int qr = lane >> 2, qk = lane & 3;
    const int wr = (wid >> 1) * 32, wc = (wid & 1) * 64;
    const int m0 = blockIdx.y * 128, n0 = blockIdx.x * 128;
    const int lr = tid >> 3, lc4 = (tid & 7) * 4;

    auto issue = [&](int kc, int st) {
        const float* Ap = A + (size_t)m0 * Hdim + kc * 32;
        const float* Wp = W + (size_t)n0 * Hdim + kc * 32;
        const uint32_t ab = s2u(As + st * GST), bb = s2u(Bs + st * GST);
#pragma unroll
        for (int p = 0; p < 4; p++) {
            const int r = lr + p * 32;
            const uint32_t so = (uint32_t)(r * GP + lc4) * 4;
            cpa16(ab + so, Ap + (size_t)r * Hdim + lc4);
            cpa16(bb + so, Wp + (size_t)r * Hdim + lc4);
        }
        CPCOMMIT();
    };

    float c[2][8][4];
#pragma unroll
    for (int mi = 0; mi < 2; mi++)
#pragma unroll
        for (int ni = 0; ni < 8; ni++)
#pragma unroll
            for (int j = 0; j < 4; j++) c[mi][ni][j] = 0.0f;

    issue(0, 0);
    for (int kc = 0; kc < 32; kc++) {
        if (kc < 31) { issue(kc + 1, (kc + 1) & 1); CPWAIT1(); }
        else         { CPWAIT0(); }
        __syncthreads();
        const float* Abuf = As + (kc & 1) * GST;
        const float* Bbuf = Bs + (kc & 1) * GST;
#pragma unroll
        for (int ks = 0; ks < 4; ks++) {
            uint32_t af[2][4], bf[8][2];
#pragma unroll
            for (int mi = 0; mi < 2; mi++) {
                const float* ap = &Abuf[(wr + 16 * mi + qr) * GP + 8 * ks + qk];
                af[mi][0] = tf32u(ap[0]);
                af[mi][1] = tf32u(ap[8 * GP]);
                af[mi][2] = tf32u(ap[4]);
                af[mi][3] = tf32u(ap[8 * GP + 4]);
            }
#pragma unroll
            for (int ni = 0; ni < 8; ni++) {
                const float* bp = &Bbuf[(wc + 8 * ni + qr) * GP + 8 * ks + qk];
                bf[ni][0] = tf32u(bp[0]);
                bf[ni][1] = tf32u(bp[4]);
            }
#pragma unroll
            for (int mi = 0; mi < 2; mi++)
#pragma unroll
                for (int ni = 0; ni < 8; ni++)
                    mma8(c[mi][ni], af[mi], bf[ni]);
        }
        __syncthreads();
    }

#pragma unroll
    for (int mi = 0; mi < 2; mi++) {
        const int row = m0 + wr + 16 * mi + qr;
#pragma unroll
        for (int ni = 0; ni < 8; ni++) {
            const int col = n0 + wc + 8 * ni + 2 * qk;
            const float b0 = bias[col], b1 = bias[col + 1];
            float o00 = c[mi][ni][0] + b0, o01 = c[mi][ni][1] + b1;
            float o10 = c[mi][ni][2] + b0, o11 = c[mi][ni][3] + b1;
            if (MODE != 0) { o00 = tf32r(o00); o01 = tf32r(o01);
                             o10 = tf32r(o10); o11 = tf32r(o11); }
            if (MODE == 3) {
                const int bq = row >> 11;
                const size_t t0 = (size_t)(row & 2047);
                float* ob = out + (size_t)(bq * 1024 + col) * 2048;
                ob[t0]            = o00;
                ob[t0 + 8]        = o10;
                ob[2048 + t0]     = o01;
                ob[2048 + t0 + 8] = o11;
            } else {
                *(float2*)(out + (size_t)row * Hdim + col) = make_float2(o00, o01);
                *(float2*)(out + (size_t)(row + 8) * Hdim + col) = make_float2(o10, o11);
            }
        }
    }
}

// ======================= fused sigmoid attention (LDS.64 frags) =======================
// Grid (32, NH, BATCH), 128 thr (4 warps), 64 q-rows/CTA, key tiles of 128.
// Effective k-order sigma(kappa) = (kappa<4 ? 2k : 2(k-4)+1) in both MMAs makes every
// B-fragment pair adjacent: K pairs (d 2qk,2qk+1) in [key][d] layout; V pairs
// (keys 2qk,2qk+1) in d-major layout (g_v written transposed by its GEMM).
// 32B-chunk XOR swizzle (chunk ^ ((row&3)<<1)) => conflict-free LDS.64.
// Smem: K 32K + V 32K = 64KB -> 3 CTAs/SM.
#define AV2   (128 * 64)
#define ASMEM (2 * 128 * 64 * 4)

template <bool WM>
__global__ void __launch_bounds__(128, 3) attn_mma(float* __restrict__ att)
{
    extern __shared__ float smr[];
    float* Ks = smr;            // [128 keys][64 d]
    float* Vs = smr + AV2;      // [64 d][128 keys]

    const int tid = threadIdx.x, wid = tid >> 5, lane = tid & 31;
    const int qr = lane >> 2, qk = lane & 3;
    const int b = blockIdx.z, h = blockIdx.y, r0 = blockIdx.x * 64;
    const int wrS = 16 * wid;

    const float* qb = g_q + (size_t)(b * Ss + r0) * Hdim + h * DH;
    const float* kb = g_k + (size_t)(b * Ss) * Hdim + h * DH;
    const float* vb = g_v + (size_t)(b * 1024 + h * DH) * 2048;  // transposed V

    const uint32_t ksb = s2u(Ks), vsb = s2u(Vs);

    auto issueK = [&](int t) {
        const float* src = kb + (size_t)t * 128 * Hdim;
#pragma unroll
        for (int p = 0; p < 16; p++) {
            const int j = tid + p * 128;
            const int row = j >> 4, cch = j & 15;           // 16B chunks, 16 per row
            const int cs = cch ^ ((row & 3) << 1);
            cpa16(ksb + (uint32_t)(row * 64 + cs * 4) * 4,
                  src + (size_t)row * Hdim + cch * 4);
        }
        CPCOMMIT();
    };
    auto issueV = [&](int t) {
        const float* src = vb + (size_t)t * 128;
#pragma unroll
        for (int p = 0; p < 16; p++) {
            const int j = tid + p * 128;
            const int d = j >> 5, cch = j & 31;             // 32 chunks per d-row
            const int cs = cch ^ ((d & 3) << 1);
            cpa16(vsb + (uint32_t)(d * 128 + cs * 4) * 4,
                  src + (size_t)d * 2048 + cch * 4);
        }
        CPCOMMIT();
    };

    issueK(0);
    issueV(0);

    // Q fragments in registers, indexed in sigma order: kappa=qk -> d=2qk, kappa=qk+4 -> d=2qk+1
    uint32_t qf[8][4];
    {
        const float* q0 = qb + (size_t)(wrS + qr) * Hdim;
        const float* q1 = q0 + 8 * (size_t)Hdim;
#pragma unroll
        for (int ks = 0; ks < 8; ks++) {
            const float2 a0 = *(const float2*)(q0 + 8 * ks + 2 * qk);
            const float2 a1 = *(const float2*)(q1 + 8 * ks + 2 * qk);
            qf[ks][0] = __float_as_uint(a0.x);
            qf[ks][1] = __float_as_uint(a1.x);
            qf[ks][2] = __float_as_uint(a0.y);
            qf[ks][3] = __float_as_uint(a1.y);
        }
    }

    float o[8][4];
#pragma unroll
    for (int ni = 0; ni < 8; ni++)
#pragma unroll
        for (int j = 0; j < 4; j++) o[ni][j] = 0.0f;

    for (int kt = 0; kt < 16; kt++) {
        CPWAIT1();        // K(kt) landed; V(kt) may still be in flight
        __syncthreads();

        // ---- S = Q @ K^T : warp tile 16 x 128, K frags via LDS.64 ----
        float s[16][4];
#pragma unroll
        for (int ni = 0; ni < 16; ni++)
#pragma unroll
            for (int j = 0; j < 4; j++) s[ni][j] = 0.0f;

#pragma unroll
        for (int ks = 0; ks < 8; ks++) {
            const int dpair = 8 * ks + 2 * qk;
#pragma unroll
            for (int ni = 0; ni < 16; ni++) {
                const int br = 8 * ni + qr;
                const float2 kk =
                    *(const float2*)&Ks[br * 64 + (dpair ^ ((br & 3) << 3))];
                uint32_t bf[2];
                bf[0] = __float_as_uint(kk.x);
                bf[1] = __float_as_uint(kk.y);
                mma8(s[ni], qf[ks], bf);
            }
        }
        __syncthreads();  // Ks consumed

        if (kt < 15) issueK(kt + 1);

        // ---- sigmoid -> att_map; P stays in registers ----
        {
            const int rr = wrS + qr;
#pragma unroll
            for (int ni = 0; ni < 16; ni++) {
                const float p0 = sigm(s[ni][0]);
                const float p1 = sigm(s[ni][1]);
                const float p2 = sigm(s[ni][2]);
                const float p3 = sigm(s[ni][3]);
                if (WM) {
                    const int cc = 8 * ni + 2 * qk;
                    size_t base = ((size_t)((b * NH + h) * Ss) + r0 + rr) * Ss
                                + (size_t)kt * 128 + cc;
                    *(float2*)(att + base) = make_float2(p0, p1);
                    *(float2*)(att + base + 8 * (size_t)Ss) = make_float2(p2, p3);
                }
                s[ni][0] = tf32r(p0);
                s[ni][1] = tf32r(p1);
                s[ni][2] = tf32r(p2);
                s[ni][3] = tf32r(p3);
            }
        }

        if (kt < 15) { CPWAIT1(); }  // V(kt) landed (K(kt+1) in flight)
        else         { CPWAIT0(); }
        __syncthreads();  // Vs visible

        // ---- O += P @ V : A = {c0,c2,c1,c3} of S; V frags via LDS.64 ----
#pragma unroll
        for (int ks = 0; ks < 16; ks++) {
            uint32_t af[4];
            af[0] = __float_as_uint(s[ks][0]);
            af[1] = __float_as_uint(s[ks][2]);
            af[2] = __float_as_uint(s[ks][1]);
            af[3] = __float_as_uint(s[ks][3]);
            const int kpair = 8 * ks + 2 * qk;
#pragma unroll
            for (int ni = 0; ni < 8; ni++) {
                const int vc = 8 * ni + qr;  // d row of Vs
                const float2 vv =
                    *(const float2*)&Vs[vc * 128 + (kpair ^ ((vc & 3) << 3))];
                uint32_t bf[2];
                bf[0] = __float_as_uint(vv.x);
                bf[1] = __float_as_uint(vv.y);
                mma8(o[ni], af, bf);
            }
        }
        __syncthreads();  // Vs consumed

        if (kt < 15) issueV(kt + 1);
    }

    // ---- write O (natural layout for the final GEMM) ----
    const int row = r0 + wrS + qr;
    float* ob = g_o + (size_t)(b * Ss + row) * Hdim + h * DH;
#pragma unroll
    for (int ni = 0; ni < 8; ni++) {
        const int col = 8 * ni + 2 * qk;
        *(float2*)(ob + col) = make_float2(o[ni][0], o[ni][1]);
        *(float2*)(ob + 8 * (size_t)Hdim + col) = make_float2(o[ni][2], o[ni][3]);
    }
}

// ---------------------------------------------------------------------------
extern "C" void kernel_launch(void* const* d_in, const int* in_sizes, int n_in,
                              void* d_out, int out_size)
{
    (void)in_sizes; (void)n_in;
    const float* v  = (const float*)d_in[0];
    const float* k  = (const float*)d_in[1];
    const float* q  = (const float*)d_in[2];
    const float* Wv = (const float*)d_in[3];
    const float* bv = (const float*)d_in[4];
    const float* Wk = (const float*)d_in[5];
    const float* bk = (const float*)d_in[6];
    const float* Wq = (const float*)d_in[7];
    const float* bq = (const float*)d_in[8];
    const float* Wm = (const float*)d_in[9];
    const float* bm = (const float*)d_in[10];
    float* out = (float*)d_out;

    float *gq, *gk, *gv, *go;
    cudaGetSymbolAddress((void**)&gq, g_q);
    cudaGetSymbolAddress((void**)&gk, g_k);
    cudaGetSymbolAddress((void**)&gv, g_v);
    cudaGetSymbolAddress((void**)&go, g_o);

    cudaFuncSetAttribute(gemm_mma<0>, cudaFuncAttributeMaxDynamicSharedMemorySize, GSMEM);
    cudaFuncSetAttribute(gemm_mma<1>, cudaFuncAttributeMaxDynamicSharedMemorySize, GSMEM);
    cudaFuncSetAttribute(gemm_mma<3>, cudaFuncAttributeMaxDynamicSharedMemorySize, GSMEM);
    cudaFuncSetAttribute(attn_mma<true>,  cudaFuncAttributeMaxDynamicSharedMemorySize, ASMEM);
    cudaFuncSetAttribute(attn_mma<false>, cudaFuncAttributeMaxDynamicSharedMemorySize, ASMEM);

    dim3 gg(Hdim / 128, MT / 128);  // (8, 32)
    gemm_mma<1><<<gg, 256, GSMEM>>>(q, Wq, bq, gq);
    gemm_mma<1><<<gg, 256, GSMEM>>>(k, Wk, bk, gk);
    gemm_mma<3><<<gg, 256, GSMEM>>>(v, Wv, bv, gv);  // writes g_v transposed

    const long long atted_elems = (long long)MT * Hdim;             // 4,194,304
    const long long map_elems   = (long long)BATCH * NH * Ss * Ss;  // 134,217,728
    dim3 ga(Ss / 64, NH, BATCH);  // (32, 16, 2)
    if ((long long)out_size >= atted_elems + map_elems) {
        attn_mma<true><<<ga, 128, ASMEM>>>(out + (size_t)atted_elems);
    } else {
        attn_mma<false><<<ga, 128, ASMEM>>>(nullptr);
    }

    gemm_mma<0><<<gg, 256, GSMEM>>>(go, Wm, bm, out);
}

// round 16
// speedup vs baseline: 1.0015x; 1.0015x over previous
#include <cuda_runtime.h>
#include <cstdint>
#include <math.h>

#define Hdim  1024
#define NH    16
#define DH    64
#define BATCH 2
#define Ss    2048
#define MT    (BATCH * Ss)

// Scratch (no allocs allowed). g_v holds V TRANSPOSED: [b*1024 + h*64 + d][token]
__device__ float g_q[MT * Hdim];
__device__ float g_k[MT * Hdim];
__device__ float g_v[MT * Hdim];
__device__ float g_o[MT * Hdim];

// ======================= helpers =======================
__device__ __forceinline__ uint32_t s2u(const void* p) {
    uint32_t a;
    asm("{ .reg .u64 t; cvta.to.shared.u64 t, %1; cvt.u32.u64 %0, t; }"
        : "=r"(a) : "l"(p));
    return a;
}
__device__ __forceinline__ float tf32r(float x) {
    uint32_t u;
    asm("cvt.rna.tf32.f32 %0, %1;" : "=r"(u) : "f"(x));
    return __uint_as_float(u);
}
__device__ __forceinline__ uint32_t tf32u(float x) {
    uint32_t u;
    asm("cvt.rna.tf32.f32 %0, %1;" : "=r"(u) : "f"(x));
    return u;
}
__device__ __forceinline__ void mma8(float* c, const uint32_t* a, const uint32_t* b) {
    asm volatile(
        "mma.sync.aligned.m16n8k8.row.col.f32.tf32.tf32.f32 "
        "{%0,%1,%2,%3}, {%4,%5,%6,%7}, {%8,%9}, {%0,%1,%2,%3};\n"
        : "+f"(c[0]), "+f"(c[1]), "+f"(c[2]), "+f"(c[3])
        : "r"(a[0]), "r"(a[1]), "r"(a[2]), "r"(a[3]), "r"(b[0]), "r"(b[1]));
}
__device__ __forceinline__ void cpa16(uint32_t dst, const void* src) {
    asm volatile("cp.async.cg.shared.global [%0], [%1], 16;" :: "r"(dst), "l"(src));
}
#define CPCOMMIT() asm volatile("cp.async.commit_group;" ::: "memory")
#define CPWAIT0()  asm volatile("cp.async.wait_group 0;" ::: "memory")
#define CPWAIT1()  asm volatile("cp.async.wait_group 1;" ::: "memory")

__device__ __forceinline__ float sigm(float x) {
    return __fdividef(1.0f, 1.0f + __expf(-0.125f * x));
}

// ======================= projection GEMM (cp.async 2-stage) =======================
// MODE 0: plain fp32 out (final proj). MODE 1: tf32-rounded out (Q, K).
// MODE 3: tf32-rounded + TRANSPOSED out for V: out[(b*1024 + col)*2048 + token].
#define GP  36
#define GST (128 * GP)
#define GSMEM (4 * GST * 4)

template <int MODE>
__global__ void __launch_bounds__(256, 2) gemm_mma(
    const float* __restrict__ A, const float* __restrict__ W,
    const float* __restrict__ bias, float* __restrict__ out)
{
    extern __shared__ float gsm[];
    float* As = gsm;             // [2][GST]
    float* Bs = gsm + 2 * GST;   // [2][GST]

    const int tid = threadIdx.x, wid = tid >> 5, lane = tid & 31;
    const int qr = lane >> 2, qk = lane & 3;
    const int wr = (wid >> 1) * 32, wc = (wid & 1) * 64;
    const int m0 = blockIdx.y * 128, n0 = blockIdx.x * 128;
    const int lr = tid >> 3, lc4 = (tid & 7) * 4;

    auto issue = [&](int kc, int st) {
        const float* Ap = A + (size_t)m0 * Hdim + kc * 32;
        const float* Wp = W + (size_t)n0 * Hdim + kc * 32;
        const uint32_t ab = s2u(As + st * GST), bb = s2u(Bs + st * GST);
#pragma unroll
        for (int p = 0; p < 4; p++) {
            const int r = lr + p * 32;
            const uint32_t so = (uint32_t)(r * GP + lc4) * 4;
            cpa16(ab + so, Ap + (size_t)r * Hdim + lc4);
            cpa16(bb + so, Wp + (size_t)r * Hdim + lc4);
        }
        CPCOMMIT();
    };

    float c[2][8][4];
#pragma unroll
    for (int mi = 0; mi < 2; mi++)
#pragma unroll
        for (int ni = 0; ni < 8; ni++)
#pragma unroll
            for (int j = 0; j < 4; j++) c[mi][ni][j] = 0.0f;

    issue(0, 0);
    for (int kc = 0; kc < 32; kc++) {
        if (kc < 31) { issue(kc + 1, (kc + 1) & 1); CPWAIT1(); }
        else         { CPWAIT0(); }
        __syncthreads();
        const float* Abuf = As + (kc & 1) * GST;
        const float* Bbuf = Bs + (kc & 1) * GST;
#pragma unroll
        for (int ks = 0; ks < 4; ks++) {
            uint32_t af[2][4], bf[8][2];
#pragma unroll
            for (int mi = 0; mi < 2; mi++) {
                const float* ap = &Abuf[(wr + 16 * mi + qr) * GP + 8 * ks + qk];
                af[mi][0] = tf32u(ap[0]);
                af[mi][1] = tf32u(ap[8 * GP]);
                af[mi][2] = tf32u(ap[4]);
                af[mi][3] = tf32u(ap[8 * GP + 4]);
            }
#pragma unroll
            for (int ni = 0; ni < 8; ni++) {
                const float* bp = &Bbuf[(wc + 8 * ni + qr) * GP + 8 * ks + qk];
                bf[ni][0] = tf32u(bp[0]);
                bf[ni][1] = tf32u(bp[4]);
            }
#pragma unroll
            for (int mi = 0; mi < 2; mi++)
#pragma unroll
                for (int ni = 0; ni < 8; ni++)
                    mma8(c[mi][ni], af[mi], bf[ni]);
        }
        __syncthreads();
    }

#pragma unroll
    for (int mi = 0; mi < 2; mi++) {
        const int row = m0 + wr + 16 * mi + qr;
#pragma unroll
        for (int ni = 0; ni < 8; ni++) {
            const int col = n0 + wc + 8 * ni + 2 * qk;
            const float b0 = bias[col], b1 = bias[col + 1];
            float o00 = c[mi][ni][0] + b0, o01 = c[mi][ni][1] + b1;
            float o10 = c[mi][ni][2] + b0, o11 = c[mi][ni][3] + b1;
            if (MODE != 0) { o00 = tf32r(o00); o01 = tf32r(o01);
                             o10 = tf32r(o10); o11 = tf32r(o11); }
            if (MODE == 3) {
                const int bq = row >> 11;
                const size_t t0 = (size_t)(row & 2047);
                float* ob = out + (size_t)(bq * 1024 + col) * 2048;
                ob[t0]            = o00;
                ob[t0 + 8]        = o10;
                ob[2048 + t0]     = o01;
                ob[2048 + t0 + 8] = o11;
            } else {
                *(float2*)(out + (size_t)row * Hdim + col) = make_float2(o00, o01);
                *(float2*)(out + (size_t)(row + 8) * Hdim + col) = make_float2(o10, o11);
            }
        }
    }
}

// ======================= fused sigmoid attention (LDS.64 frags) =======================
// Grid (32, NH, BATCH), 128 thr (4 warps), 64 q-rows/CTA, key tiles of 128.
// Effective k-order sigma(kappa) = (kappa<4 ? 2k : 2(k-4)+1) in both MMAs makes every
// B-fragment pair adjacent: K pairs (d 2qk,2qk+1) in [key][d] layout; V pairs
// (keys 2qk,2qk+1) in d-major layout (g_v written transposed by its GEMM).
// 32B-chunk XOR swizzle (chunk ^ ((row&3)<<1)) => conflict-free LDS.64.
// Smem: K 32K + V 32K = 64KB -> 3 CTAs/SM.
#define AV2   (128 * 64)
#define ASMEM (2 * 128 * 64 * 4)

template <bool WM>
__global__ void __launch_bounds__(128, 3) attn_mma(float* __restrict__ att)
{
    extern __shared__ float smr[];
    float* Ks = smr;            // [128 keys][64 d]
    float* Vs = smr + AV2;      // [64 d][128 keys]

    const int tid = threadIdx.x, wid = tid >> 5, lane = tid & 31;
    const int qr = lane >> 2, qk = lane & 3;
    const int b = blockIdx.z, h = blockIdx.y, r0 = blockIdx.x * 64;
    const int wrS = 16 * wid;

    const float* qb = g_q + (size_t)(b * Ss + r0) * Hdim + h * DH;
    const float* kb = g_k + (size_t)(b * Ss) * Hdim + h * DH;
    const float* vb = g_v + (size_t)(b * 1024 + h * DH) * 2048;  // transposed V

    const uint32_t ksb = s2u(Ks), vsb = s2u(Vs);

    auto issueK = [&](int t) {
        const float* src = kb + (size_t)t * 128 * Hdim;
#pragma unroll
        for (int p = 0; p < 16; p++) {
            const int j = tid + p * 128;
            const int row = j >> 4, cch = j & 15;           // 16B chunks, 16 per row
            const int cs = cch ^ ((row & 3) << 1);
            cpa16(ksb + (uint32_t)(row * 64 + cs * 4) * 4,
                  src + (size_t)row * Hdim + cch * 4);
        }
        CPCOMMIT();
    };
    auto issueV = [&](int t) {
        const float* src = vb + (size_t)t * 128;
#pragma unroll
        for (int p = 0; p < 16; p++) {
            const int j = tid + p * 128;
            const int d = j >> 5, cch = j & 31;             // 32 chunks per d-row
            const int cs = cch ^ ((d & 3) << 1);
            cpa16(vsb + (uint32_t)(d * 128 + cs * 4) * 4,
                  src + (size_t)d * 2048 + cch * 4);
        }
        CPCOMMIT();
    };

    issueK(0);
    issueV(0);

    // Q fragments in registers, indexed in sigma order: kappa=qk -> d=2qk, kappa=qk+4 -> d=2qk+1
    uint32_t qf[8][4];
    {
        const float* q0 = qb + (size_t)(wrS + qr) * Hdim;
        const float* q1 = q0 + 8 * (size_t)Hdim;
#pragma unroll
        for (int ks = 0; ks < 8; ks++) {
            const float2 a0 = *(const float2*)(q0 + 8 * ks + 2 * qk);
            const float2 a1 = *(const float2*)(q1 + 8 * ks + 2 * qk);
            qf[ks][0] = __float_as_uint(a0.x);
            qf[ks][1] = __float_as_uint(a1.x);
            qf[ks][2] = __float_as_uint(a0.y);
            qf[ks][3] = __float_as_uint(a1.y);
        }
    }

    float o[8][4];
#pragma unroll
    for (int ni = 0; ni < 8; ni++)
#pragma unroll
        for (int j = 0; j < 4; j++) o[ni][j] = 0.0f;

    for (int kt = 0; kt < 16; kt++) {
        CPWAIT1();        // K(kt) landed; V(kt) may still be in flight
        __syncthreads();

        // ---- S = Q @ K^T : warp tile 16 x 128, K frags via LDS.64 ----
        float s[16][4];
#pragma unroll
        for (int ni = 0; ni < 16; ni++)
#pragma unroll
            for (int j = 0; j < 4; j++) s[ni][j] = 0.0f;

#pragma unroll
        for (int ks = 0; ks < 8; ks++) {
            const int dpair = 8 * ks + 2 * qk;
#pragma unroll
            for (int ni = 0; ni < 16; ni++) {
                const int br = 8 * ni + qr;
                const float2 kk =
                    *(const float2*)&Ks[br * 64 + (dpair ^ ((br & 3) << 3))];
                uint32_t bf[2];
                bf[0] = __float_as_uint(kk.x);
                bf[1] = __float_as_uint(kk.y);
                mma8(s[ni], qf[ks], bf);
            }
        }
        __syncthreads();  // Ks consumed

        if (kt < 15) issueK(kt + 1);

        // ---- sigmoid -> att_map; P stays in registers ----
        {
            const int rr = wrS + qr;
#pragma unroll
            for (int ni = 0; ni < 16; ni++) {
                const float p0 = sigm(s[ni][0]);
                const float p1 = sigm(s[ni][1]);
                const float p2 = sigm(s[ni][2]);
                const float p3 = sigm(s[ni][3]);
                if (WM) {
                    const int cc = 8 * ni + 2 * qk;
                    size_t base = ((size_t)((b * NH + h) * Ss) + r0 + rr) * Ss
                                + (size_t)kt * 128 + cc;
                    *(float2*)(att + base) = make_float2(p0, p1);
                    *(float2*)(att + base + 8 * (size_t)Ss) = make_float2(p2, p3);
                }
                s[ni][0] = tf32r(p0);
                s[ni][1] = tf32r(p1);
                s[ni][2] = tf32r(p2);
                s[ni][3] = tf32r(p3);
            }
        }

        if (kt < 15) { CPWAIT1(); }  // V(kt) landed (K(kt+1) in flight)
        else         { CPWAIT0(); }
        __syncthreads();  // Vs visible

        // ---- O += P @ V : A = {c0,c2,c1,c3} of S; V frags via LDS.64 ----
#pragma unroll
        for (int ks = 0; ks < 16; ks++) {
            uint32_t af[4];
            af[0] = __float_as_uint(s[ks][0]);
            af[1] = __float_as_uint(s[ks][2]);
            af[2] = __float_as_uint(s[ks][1]);
            af[3] = __float_as_uint(s[ks][3]);
            const int kpair = 8 * ks + 2 * qk;
#pragma unroll
            for (int ni = 0; ni < 8; ni++) {
                const int vc = 8 * ni + qr;  // d row of Vs
                const float2 vv =
                    *(const float2*)&Vs[vc * 128 + (kpair ^ ((vc & 3) << 3))];
                uint32_t bf[2];
                bf[0] = __float_as_uint(vv.x);
                bf[1] = __float_as_uint(vv.y);
                mma8(o[ni], af, bf);
            }
        }
        __syncthreads();  // Vs consumed

        if (kt < 15) issueV(kt + 1);
    }

    // ---- write O (natural layout for the final GEMM) ----
    const int row = r0 + wrS + qr;
    float* ob = g_o + (size_t)(b * Ss + row) * Hdim + h * DH;
#pragma unroll
    for (int ni = 0; ni < 8; ni++) {
        const int col = 8 * ni + 2 * qk;
        *(float2*)(ob + col) = make_float2(o[ni][0], o[ni][1]);
        *(float2*)(ob + 8 * (size_t)Hdim + col) = make_float2(o[ni][2], o[ni][3]);
    }
}

// ---------------------------------------------------------------------------
extern "C" void kernel_launch(void* const* d_in, const int* in_sizes, int n_in,
                              void* d_out, int out_size)
{
    (void)in_sizes; (void)n_in;
    const float* v  = (const float*)d_in[0];
    const float* k  = (const float*)d_in[1];
    const float* q  = (const float*)d_in[2];
    const float* Wv = (const float*)d_in[3];
    const float* bv = (const float*)d_in[4];
    const float* Wk = (const float*)d_in[5];
    const float* bk = (const float*)d_in[6];
    const float* Wq = (const float*)d_in[7];
    const float* bq = (const float*)d_in[8];
    const float* Wm = (const float*)d_in[9];
    const float* bm = (const float*)d_in[10];
    float* out = (float*)d_out;

    float *gq, *gk, *gv, *go;
    cudaGetSymbolAddress((void**)&gq, g_q);
    cudaGetSymbolAddress((void**)&gk, g_k);
    cudaGetSymbolAddress((void**)&gv, g_v);
    cudaGetSymbolAddress((void**)&go, g_o);

    cudaFuncSetAttribute(gemm_mma<0>, cudaFuncAttributeMaxDynamicSharedMemorySize, GSMEM);
    cudaFuncSetAttribute(gemm_mma<1>, cudaFuncAttributeMaxDynamicSharedMemorySize, GSMEM);
    cudaFuncSetAttribute(gemm_mma<3>, cudaFuncAttributeMaxDynamicSharedMemorySize, GSMEM);
    cudaFuncSetAttribute(attn_mma<true>,  cudaFuncAttributeMaxDynamicSharedMemorySize, ASMEM);
    cudaFuncSetAttribute(attn_mma<false>, cudaFuncAttributeMaxDynamicSharedMemorySize, ASMEM);

    dim3 gg(Hdim / 128, MT / 128);  // (8, 32)
    gemm_mma<1><<<gg, 256, GSMEM>>>(q, Wq, bq, gq);
    gemm_mma<1><<<gg, 256, GSMEM>>>(k, Wk, bk, gk);
    gemm_mma<3><<<gg, 256, GSMEM>>>(v, Wv, bv, gv);  // writes g_v transposed

    const long long atted_elems = (long long)MT * Hdim;             // 4,194,304
    const long long map_elems   = (long long)BATCH * NH * Ss * Ss;  // 134,217,728
    dim3 ga(Ss / 64, NH, BATCH);  // (32, 16, 2)
    if ((long long)out_size >= atted_elems + map_elems) {
        attn_mma<true><<<ga, 128, ASMEM>>>(out + (size_t)atted_elems);
    } else {
        attn_mma<false><<<ga, 128, ASMEM>>>(nullptr);
    }

    gemm_mma<0><<<gg, 256, GSMEM>>>(go, Wm, bm, out);
}

// round 17
// speedup vs baseline: 1.7903x; 1.7875x over previous
#include <cuda_runtime.h>
#include <cuda_fp16.h>
#include <cstdint>
#include <math.h>

#define Hdim  1024
#define NH    16
#define DH    64
#define BATCH 2
#define Ss    2048
#define MT    (BATCH * Ss)

// fp16 scratch (no allocs allowed)
__device__ __half g_iq[MT * Hdim];   // fp16 copy of input q
__device__ __half g_ik[MT * Hdim];
__device__ __half g_iv[MT * Hdim];
__device__ __half g_wqh[Hdim * Hdim];
__device__ __half g_wkh[Hdim * Hdim];
__device__ __half g_wvh[Hdim * Hdim];
__device__ __half g_wmh[Hdim * Hdim];
__device__ __half g_qh[MT * Hdim];   // projected Q (fp16)
__device__ __half g_kh[MT * Hdim];   // projected K (fp16)
__device__ __half g_vh[MT * Hdim];   // projected V, TRANSPOSED [b*1024+h*64+d][token]
__device__ __half g_oh[MT * Hdim];   // atted (fp16), natural layout

// ======================= helpers =======================
__device__ __forceinline__ uint32_t s2u(const void* p) {
    uint32_t a;
    asm("{ .reg .u64 t; cvta.to.shared.u64 t, %1; cvt.u32.u64 %0, t; }"
        : "=r"(a) : "l"(p));
    return a;
}
__device__ __forceinline__ uint32_t pack2(float a, float b) {
    __half2 h = __floats2half2_rn(a, b);
    return *(uint32_t*)&h;
}
__device__ __forceinline__ void mma16(float* c, const uint32_t* a, const uint32_t* b) {
    asm volatile(
        "mma.sync.aligned.m16n8k16.row.col.f32.f16.f16.f32 "
        "{%0,%1,%2,%3}, {%4,%5,%6,%7}, {%8,%9}, {%0,%1,%2,%3};\n"
        : "+f"(c[0]), "+f"(c[1]), "+f"(c[2]), "+f"(c[3])
        : "r"(a[0]), "r"(a[1]), "r"(a[2]), "r"(a[3]), "r"(b[0]), "r"(b[1]));
}
__device__ __forceinline__ void cpa16(uint32_t dst, const void* src) {
    asm volatile("cp.async.cg.shared.global [%0], [%1], 16;" :: "r"(dst), "l"(src));
}
#define CPCOMMIT() asm volatile("cp.async.commit_group;" ::: "memory")
#define CPWAIT0()  asm volatile("cp.async.wait_group 0;" ::: "memory")

__device__ __forceinline__ float sigm(float x) {
    return __fdividef(1.0f, 1.0f + __expf(-0.125f * x));
}

// ======================= fp32 -> fp16 convert =======================
__global__ void __launch_bounds__(256) cvt_f2h(const float* __restrict__ s,
                                               __half* __restrict__ d) {
    const int i = (blockIdx.x * 256 + threadIdx.x) * 8;
    float4 a = *(const float4*)(s + i);
    float4 b = *(const float4*)(s + i + 4);
    uint4 o;
    o.x = pack2(a.x, a.y); o.y = pack2(a.z, a.w);
    o.z = pack2(b.x, b.y); o.w = pack2(b.z, b.w);
    *(uint4*)(d + i) = o;
}

// ======================= fp16 projection GEMM =======================
// out[M,N] = A[M,K] @ W[N,K]^T + bias. CTA 128x128, BK=64, 256 thr, 2-stage.
// Smem tiles [row][64 halves = 128B = 8 c16], swizzle c16 ^ (row&7).
// MODE 0: fp32 out; MODE 1: fp16 out; MODE 3: fp16 transposed out (V).
#define HST (128 * 64)            // halves per tile
#define GSMEMH (4 * HST * 2)      // 2 stages x (A+B) = 64KB

template <int MODE>
__global__ void __launch_bounds__(256, 2) gemm_h(
    const __half* __restrict__ A, const __half* __restrict__ W,
    const float* __restrict__ bias, void* __restrict__ outp)
{
    extern __shared__ __half hsm[];
    __half* As = hsm;              // [2][HST]
    __half* Bs = hsm + 2 * HST;    // [2][HST]

    const int tid = threadIdx.x, wid = tid >> 5, lane = tid & 31;
    const int qr = lane >> 2, qk = lane & 3;
    const int wr = (wid >> 1) * 32, wc = (wid & 1) * 64;
    const int m0 = blockIdx.y * 128, n0 = blockIdx.x * 128;

    auto issue = [&](int kc) {
        const int st = kc & 1;
        const __half* Ap = A + (size_t)m0 * Hdim + kc * 64;
        const __half* Wp = W + (size_t)n0 * Hdim + kc * 64;
        const uint32_t ab = s2u(As + st * HST), bb = s2u(Bs + st * HST);
#pragma unroll
        for (int p = 0; p < 8; p++) {
            const int j = (tid + p * 256) & 1023;
            const int row = j >> 3, c16 = j & 7;
            const uint32_t so = (uint32_t)(row * 128 + ((c16 ^ (row & 7)) << 4));
            if (p < 4) cpa16(ab + so, Ap + (size_t)row * Hdim + c16 * 8);
            else       cpa16(bb + so, Wp + (size_t)row * Hdim + c16 * 8);
        }
        CPCOMMIT();
    };

    float c[2][8][4];
#pragma unroll
    for (int mi = 0; mi < 2; mi++)
#pragma unroll
        for (int ni = 0; ni < 8; ni++)
#pragma unroll
            for (int j = 0; j < 4; j++) c[mi][ni][j] = 0.0f;

    issue(0);
    for (int kc = 0; kc < 16; kc++) {
        CPWAIT0();
        __syncthreads();
        if (kc < 15) issue(kc + 1);
        const __half* Ab = As + (kc & 1) * HST;
        const __half* Bb = Bs + (kc & 1) * HST;
#pragma unroll
        for (int ks = 0; ks < 4; ks++) {     // 4 k16 steps in BK=64
            uint32_t af[2][4], bf[8][2];
#pragma unroll
            for (int mi = 0; mi < 2; mi++) {
                const int r0 = wr + 16 * mi + qr, r1 = r0 + 8;
                const int swz0 = ((2 * ks) ^ (qr & 7)) << 3;
                const int swz1 = ((2 * ks + 1) ^ (qr & 7)) << 3;
                af[mi][0] = *(const uint32_t*)&Ab[r0 * 64 + swz0 + 2 * qk];
                af[mi][1] = *(const uint32_t*)&Ab[r1 * 64 + swz0 + 2 * qk];
                af[mi][2] = *(const uint32_t*)&Ab[r0 * 64 + swz1 + 2 * qk];
                af[mi][3] = *(const uint32_t*)&Ab[r1 * 64 + swz1 + 2 * qk];
            }
#pragma unroll
            for (int ni = 0; ni < 8; ni++) {
                const int br = wc + 8 * ni + qr;
                bf[ni][0] = *(const uint32_t*)&Bb[br * 64 + (((2 * ks) ^ (qr & 7)) << 3) + 2 * qk];
                bf[ni][1] = *(const uint32_t*)&Bb[br * 64 + (((2 * ks + 1) ^ (qr & 7)) << 3) + 2 * qk];
            }
#pragma unroll
            for (int mi = 0; mi < 2; mi++)
#pragma unroll
                for (int ni = 0; ni < 8; ni++)
                    mma16(c[mi][ni], af[mi], bf[ni]);
        }
        __syncthreads();
    }

#pragma unroll
    for (int mi = 0; mi < 2; mi++) {
        const int row = m0 + wr + 16 * mi + qr;
#pragma unroll
        for (int ni = 0; ni < 8; ni++) {
            const int col = n0 + wc + 8 * ni + 2 * qk;
            const float b0 = bias[col], b1 = bias[col + 1];
            const float o00 = c[mi][ni][0] + b0, o01 = c[mi][ni][1] + b1;
            const float o10 = c[mi][ni][2] + b0, o11 = c[mi][ni][3] + b1;
            if (MODE == 0) {
                float* out = (float*)outp;
                *(float2*)(out + (size_t)row * Hdim + col) = make_float2(o00, o01);
                *(float2*)(out + (size_t)(row + 8) * Hdim + col) = make_float2(o10, o11);
            } else if (MODE == 1) {
                __half* out = (__half*)outp;
                *(uint32_t*)(out + (size_t)row * Hdim + col) = pack2(o00, o01);
                *(uint32_t*)(out + (size_t)(row + 8) * Hdim + col) = pack2(o10, o11);
            } else {
                __half* out = (__half*)outp;
                const int bq = row >> 11;
                const size_t t0 = (size_t)(row & 2047);
                __half* ob = out + (size_t)(bq * 1024 + col) * 2048;
                ob[t0]            = __float2half_rn(o00);
                ob[t0 + 8]        = __float2half_rn(o10);
                ob[2048 + t0]     = __float2half_rn(o01);
                ob[2048 + t0 + 8] = __float2half_rn(o11);
            }
        }
    }
}

// ======================= fused sigmoid attention (fp16) =======================
// Grid (32, NH, BATCH), 128 thr (4 warps), 64 q-rows/CTA, key tiles of 128.
// Ks [128 keys][64 d] fp16 16KB; Vs [64 d][128 keys] fp16 16KB; double-buffered.
// m16n8k16: S C-frags map identically onto PV A-frags (no smem P, no permutes).
#define AKH (128 * 64)
#define AVH (128 * 64)
#define ASMEMH ((2 * AKH + 2 * AVH) * 2)   // 64KB

template <bool WM>
__global__ void __launch_bounds__(128, 3) attn_h(float* __restrict__ att)
{
    extern __shared__ __half hs[];
    __half* Ks = hs;                 // [2][AKH]
    __half* Vs = hs + 2 * AKH;       // [2][AVH]

    const int tid = threadIdx.x, wid = tid >> 5, lane = tid & 31;
    const int qr = lane >> 2, qk = lane & 3;
    const int b = blockIdx.z, h = blockIdx.y, r0 = blockIdx.x * 64;
    const int wrS = 16 * wid;

    const __half* qb = g_qh + (size_t)(b * Ss + r0) * Hdim + h * DH;
    const __half* kb = g_kh + (size_t)(b * Ss) * Hdim + h * DH;
    const __half* vb = g_vh + (size_t)(b * 1024 + h * DH) * 2048;

    auto issueKV = [&](int t) {
        const int st = t & 1;
        const __half* ksrc = kb + (size_t)t * 128 * Hdim;
        const __half* vsrc = vb + (size_t)t * 128;
        const uint32_t kd = s2u(Ks + st * AKH), vd = s2u(Vs + st * AVH);
#pragma unroll
        for (int p = 0; p < 8; p++) {        // K: 1024 chunks
            const int j = tid + p * 128;
            const int row = j >> 3, c16 = j & 7;
            cpa16(kd + (uint32_t)(row * 128 + ((c16 ^ (row & 7)) << 4)),
                  ksrc + (size_t)row * Hdim + c16 * 8);
        }
#pragma unroll
        for (int p = 0; p < 8; p++) {        // V: 1024 chunks
            const int j = tid + p * 128;
            const int d = j >> 4, c16 = j & 15;
            cpa16(vd + (uint32_t)(d * 256 + ((c16 ^ (d & 7)) << 4)),
                  vsrc + (size_t)d * 2048 + c16 * 8);
        }
        CPCOMMIT();
    };

    // Q fragments in registers: qf[ks] = A-frag for k16 step ks (d 16ks..16ks+15)
    uint32_t qf[4][4];
    {
        const __half* q0 = qb + (size_t)(wrS + qr) * Hdim;
        const __half* q1 = q0 + 8 * (size_t)Hdim;
#pragma unroll
        for (int ks = 0; ks < 4; ks++) {
            qf[ks][0] = *(const uint32_t*)(q0 + 16 * ks + 2 * qk);
            qf[ks][1] = *(const uint32_t*)(q1 + 16 * ks + 2 * qk);
            qf[ks][2] = *(const uint32_t*)(q0 + 16 * ks + 2 * qk + 8);
            qf[ks][3] = *(const uint32_t*)(q1 + 16 * ks + 2 * qk + 8);
        }
    }

    issueKV(0);

    float o[8][4];
#pragma unroll
    for (int ni = 0; ni < 8; ni++)
#pragma unroll
        for (int j = 0; j < 4; j++) o[ni][j] = 0.0f;

    for (int kt = 0; kt < 16; kt++) {
        CPWAIT0();
        __syncthreads();               // tile kt visible; tile kt-1 reads done by all
        if (kt < 15) issueKV(kt + 1);  // into buffer consumed at kt-1

        const __half* Kt = Ks + (kt & 1) * AKH;
        const __half* Vt = Vs + (kt & 1) * AVH;

        // ---- S = Q @ K^T : warp tile 16 x 128 ----
        float s[16][4];
#pragma unroll
        for (int ni = 0; ni < 16; ni++)
#pragma unroll
            for (int j = 0; j < 4; j++) s[ni][j] = 0.0f;

#pragma unroll
        for (int ks = 0; ks < 4; ks++) {
            const int sw0 = ((2 * ks) ^ 0) << 3;        // c16 base (row-xor added below)
            const int sw1 = ((2 * ks + 1) ^ 0) << 3;
            (void)sw0; (void)sw1;
#pragma unroll
            for (int ni = 0; ni < 16; ni++) {
                const int key = 8 * ni + qr;
                uint32_t bf[2];
                bf[0] = *(const uint32_t*)&Kt[key * 64 + (((2 * ks) ^ (key & 7)) << 3) + 2 * qk];
                bf[1] = *(const uint32_t*)&Kt[key * 64 + (((2 * ks + 1) ^ (key & 7)) << 3) + 2 * qk];
                mma16(s[ni], qf[ks], bf);
            }
        }

        // ---- sigmoid -> att_map (fp32) ; P packed to fp16 in registers ----
        uint32_t pf[16][2];
        {
            const int rr = wrS + qr;
#pragma unroll
            for (int ni = 0; ni < 16; ni++) {
                const float p0 = sigm(s[ni][0]);
                const float p1 = sigm(s[ni][1]);
                const float p2 = sigm(s[ni][2]);
                const float p3 = sigm(s[ni][3]);
                if (WM) {
                    const int cc = 8 * ni + 2 * qk;
                    size_t base = ((size_t)((b * NH + h) * Ss) + r0 + rr) * Ss
                                + (size_t)kt * 128 + cc;
                    *(float2*)(att + base) = make_float2(p0, p1);
                    *(float2*)(att + base + 8 * (size_t)Ss) = make_float2(p2, p3);
                }
                pf[ni][0] = pack2(p0, p1);   // row qr,   keys 8ni+2qk, +1
                pf[ni][1] = pack2(p2, p3);   // row qr+8
            }
        }

        // ---- O += P @ V : A-frag identity from S C-frags; V via 2x LDS.32 ----
#pragma unroll
        for (int ks = 0; ks < 8; ks++) {     // 8 k16 steps over 128 keys
            uint32_t af[4];
            af[0] = pf[2 * ks][0];
            af[1] = pf[2 * ks][1];
            af[2] = pf[2 * ks + 1][0];
            af[3] = pf[2 * ks + 1][1];
#pragma unroll
            for (int ni = 0; ni < 8; ni++) {
                const int d = 8 * ni + qr;
                uint32_t bf[2];
                bf[0] = *(const uint32_t*)&Vt[d * 128 + (((2 * ks) ^ (d & 7)) << 3) + 2 * qk];
                bf[1] = *(const uint32_t*)&Vt[d * 128 + (((2 * ks + 1) ^ (d & 7)) << 3) + 2 * qk];
                mma16(o[ni], af, bf);
            }
        }
    }

    // ---- write O (fp16, natural layout) ----
    const int row = r0 + wrS + qr;
    __half* ob = g_oh + (size_t)(b * Ss + row) * Hdim + h * DH;
#pragma unroll
    for (int ni = 0; ni < 8; ni++) {
        const int col = 8 * ni + 2 * qk;
        *(uint32_t*)(ob + col) = pack2(o[ni][0], o[ni][1]);
        *(uint32_t*)(ob + 8 * (size_t)Hdim + col) = pack2(o[ni][2], o[ni][3]);
    }
}

// ---------------------------------------------------------------------------
extern "C" void kernel_launch(void* const* d_in, const int* in_sizes, int n_in,
                              void* d_out, int out_size)
{
    (void)in_sizes; (void)n_in;
    const float* v  = (const float*)d_in[0];
    const float* k  = (const float*)d_in[1];
    const float* q  = (const float*)d_in[2];
    const float* Wv = (const float*)d_in[3];
    const float* bv = (const float*)d_in[4];
    const float* Wk = (const float*)d_in[5];
    const float* bk = (const float*)d_in[6];
    const float* Wq = (const float*)d_in[7];
    const float* bq = (const float*)d_in[8];
    const float* Wm = (const float*)d_in[9];
    const float* bm = (const float*)d_in[10];
    float* out = (float*)d_out;

    __half *iq, *ik, *iv, *wqh, *wkh, *wvh, *wmh, *qh, *kh, *vh, *oh;
    cudaGetSymbolAddress((void**)&iq,  g_iq);
    cudaGetSymbolAddress((void**)&ik,  g_ik);
    cudaGetSymbolAddress((void**)&iv,  g_iv);
    cudaGetSymbolAddress((void**)&wqh, g_wqh);
    cudaGetSymbolAddress((void**)&wkh, g_wkh);
    cudaGetSymbolAddress((void**)&wvh, g_wvh);
    cudaGetSymbolAddress((void**)&wmh, g_wmh);
    cudaGetSymbolAddress((void**)&qh,  g_qh);
    cudaGetSymbolAddress((void**)&kh,  g_kh);
    cudaGetSymbolAddress((void**)&vh,  g_vh);
    cudaGetSymbolAddress((void**)&oh,  g_oh);

    cudaFuncSetAttribute(gemm_h<0>, cudaFuncAttributeMaxDynamicSharedMemorySize, GSMEMH);
    cudaFuncSetAttribute(gemm_h<1>, cudaFuncAttributeMaxDynamicSharedMemorySize, GSMEMH);
    cudaFuncSetAttribute(gemm_h<3>, cudaFuncAttributeMaxDynamicSharedMemorySize, GSMEMH);
    cudaFuncSetAttribute(attn_h<true>,  cudaFuncAttributeMaxDynamicSharedMemorySize, ASMEMH);
    cudaFuncSetAttribute(attn_h<false>, cudaFuncAttributeMaxDynamicSharedMemorySize, ASMEMH);

    const int NI = MT * Hdim / 2048;    // 2048 elems per block
    const int NW = Hdim * Hdim / 2048;
    cvt_f2h<<<NI, 256>>>(q, iq);
    cvt_f2h<<<NI, 256>>>(k, ik);
    cvt_f2h<<<NI, 256>>>(v, iv);
    cvt_f2h<<<NW, 256>>>(Wq, wqh);
    cvt_f2h<<<NW, 256>>>(Wk, wkh);
    cvt_f2h<<<NW, 256>>>(Wv, wvh);
    cvt_f2h<<<NW, 256>>>(Wm, wmh);

    dim3 gg(Hdim / 128, MT / 128);  // (8, 32)
    gemm_h<1><<<gg, 256, GSMEMH>>>(iq, wqh, bq, qh);
    gemm_h<1><<<gg, 256, GSMEMH>>>(ik, wkh, bk, kh);
    gemm_h<3><<<gg, 256, GSMEMH>>>(iv, wvh, bv, vh);   // transposed fp16 V

    const long long atted_elems = (long long)MT * Hdim;             // 4,194,304
    const long long map_elems   = (long long)BATCH * NH * Ss * Ss;  // 134,217,728
    dim3 ga(Ss / 64, NH, BATCH);  // (32, 16, 2)
    if ((long long)out_size >= atted_elems + map_elems) {
        attn_h<true><<<ga, 128, ASMEMH>>>(out + (size_t)atted_elems);
    } else {
        attn_h<false><<<ga, 128, ASMEMH>>>(nullptr);
    }

    gemm_h<0><<<gg, 256, GSMEMH>>>(oh, wmh, bm, out);
}